// round 4
// baseline (speedup 1.0000x reference)
#include <cuda_runtime.h>

// Single-pass IndRNN scan with decoupled lookback.
// h_t = relu(x_t + w*h_{t-1}), w >= 0.
// Per chunk of L steps the map collapses exactly to h_out = max(M, A + w^L*h_in):
//   M' = max(0, x + w*M)  (M0 = -inf for w>0, else 0),  A' = x + w*A.
// Block (tile,k): 256 channels x L=32 timesteps, x kept in registers; waits for
// predecessor chunk's h via L2 flag, publishes its own h, then emits outputs.
// Reads x ONCE (vs twice in the 3-kernel version).

static constexpr int T     = 2048;
static constexpr int B     = 32;
static constexpr int H     = 1024;
static constexpr int BH    = B * H;        // 32768
static constexpr int L     = 32;           // timesteps per chunk (in registers)
static constexpr int K     = T / L;        // 64 chunks
static constexpr int TILES = BH / 256;     // 128 channel tiles
static constexpr int NBLK  = TILES * K;    // 8192 blocks

__device__ float    g_hout[(size_t)K * BH];   // published h at end of chunk k
__device__ int      g_flag[NBLK];             // [k*TILES + tile], self-cleaning
__device__ unsigned g_ticket;                 // scheduling-order tickets
__device__ unsigned g_done;                   // for end-of-launch cleanup

__global__ __launch_bounds__(256)
void indrnn_onepass(const float* __restrict__ x,
                    const float* __restrict__ h0,
                    const float* __restrict__ w,
                    float* __restrict__ out)
{
    __shared__ unsigned s_vid;
    if (threadIdx.x == 0) s_vid = atomicAdd(&g_ticket, 1u);
    __syncthreads();
    const unsigned vid = s_vid;
    const int tile = vid & (TILES - 1);
    const int k    = vid >> 7;                       // TILES = 2^7
    const int c    = tile * 256 + threadIdx.x;

    const float wc = __ldg(&w[c & (H - 1)]);
    const float* xp = x + (size_t)k * L * BH + c;

    // Load the whole chunk into registers (the only read of x).
    float buf[L];
#pragma unroll
    for (int i = 0; i < L; i++) buf[i] = __ldcs(xp + i * BH);

    // Chunk summary: h_out = max(M, A + P*h_in)
    float M = (wc > 0.0f) ? __int_as_float(0xff800000) : 0.0f;  // -inf / 0
    float A = 0.0f;
#pragma unroll
    for (int i = 0; i < L; i++) {
        M = fmaxf(0.0f, fmaf(wc, M, buf[i]));
        A = fmaf(wc, A, buf[i]);
    }

    // Acquire h_in from predecessor chunk (same tile).
    float hin;
    if (k == 0) {
        hin = __ldg(&h0[c]);
    } else {
        if (threadIdx.x == 0) {
            volatile int* f = &g_flag[(k - 1) * TILES + tile];
            while (*f == 0) { __nanosleep(32); }
            __threadfence();
        }
        __syncthreads();
        hin = __ldcg(&g_hout[(size_t)(k - 1) * BH + c]);
    }

    // Publish FIRST (chain critical path), then emit.
    if (k < K - 1) {
        float P = wc;
#pragma unroll
        for (int s = 0; s < 5; s++) P *= P;          // wc^32
        __stcg(&g_hout[(size_t)k * BH + c], fmaxf(M, fmaf(P, hin, A)));
        __threadfence();
        __syncthreads();                              // all values + fences done
        if (threadIdx.x == 0) g_flag[k * TILES + tile] = 1;
    } else {
        __syncthreads();                              // all threads read hin
    }
    // Reset the flag we consumed (self-cleaning for graph replays).
    if (k > 0 && threadIdx.x == 0) g_flag[(k - 1) * TILES + tile] = 0;

    // Emit: exact forward recursion from registers.
    float* op = out + (size_t)k * L * BH + c;
    float h = hin;
#pragma unroll
    for (int i = 0; i < L; i++) {
        h = fmaxf(fmaf(wc, h, buf[i]), 0.0f);
        __stcs(op + i * BH, h);
    }

    // Last block to finish resets ticket/done for the next launch.
    __syncthreads();
    if (threadIdx.x == 0) {
        unsigned d = atomicAdd(&g_done, 1u);
        if (d == NBLK - 1) { g_ticket = 0; g_done = 0; __threadfence(); }
    }
}

extern "C" void kernel_launch(void* const* d_in, const int* in_sizes, int n_in,
                              void* d_out, int out_size)
{
    const float* x  = (const float*)d_in[0];   // (T, B, H)
    const float* h0 = (const float*)d_in[1];   // (B, H)
    const float* w  = (const float*)d_in[2];   // (H,)
    float* out      = (float*)d_out;

    indrnn_onepass<<<NBLK, 256>>>(x, h0, w, out);
}

// round 6
// speedup vs baseline: 1.3860x; 1.3860x over previous
#include <cuda_runtime.h>

// Single-pass IndRNN scan, decoupled lookback with per-lane packed
// {epoch, value} 64-bit release/acquire slots (CUB ScanTileState style).
// h_t = relu(x_t + w*h_{t-1}), w >= 0. Chunk map: h_out = max(M, A + w^L*h_in).
// Traffic: x read once (256MB) + out (256MB) + 8MB publish = ~520MB.

static constexpr int T     = 2048;
static constexpr int B     = 32;
static constexpr int H     = 1024;
static constexpr int BH    = B * H;        // 32768
static constexpr int L     = 32;           // timesteps per chunk (registers)
static constexpr int K     = T / L;        // 64 chunks
static constexpr int TILES = BH / 256;     // 128 channel tiles
static constexpr int NBLK  = TILES * K;    // 8192 blocks

// Packed slot: high 32 = epoch flag, low 32 = float bits of h.
__device__ unsigned long long g_slot[(size_t)K * BH];   // 16 MB
__device__ unsigned           g_epoch;
__device__ unsigned           g_ticket;

__global__ void k_prologue()
{
    g_epoch  = g_epoch + 1u;
    g_ticket = 0u;
}

__device__ __forceinline__ void st_release_u64(unsigned long long* p,
                                               unsigned long long v)
{
    asm volatile("st.release.gpu.global.u64 [%0], %1;" :: "l"(p), "l"(v) : "memory");
}
__device__ __forceinline__ unsigned long long ld_acquire_u64(
    const unsigned long long* p)
{
    unsigned long long v;
    asm volatile("ld.acquire.gpu.global.u64 %0, [%1];" : "=l"(v) : "l"(p) : "memory");
    return v;
}

__global__ __launch_bounds__(256)
void indrnn_onepass(const float* __restrict__ x,
                    const float* __restrict__ h0,
                    const float* __restrict__ w,
                    float* __restrict__ out)
{
    __shared__ unsigned s_vid;
    if (threadIdx.x == 0) s_vid = atomicAdd(&g_ticket, 1u);
    __syncthreads();
    const unsigned vid = s_vid;
    const int tile = vid & (TILES - 1);
    const int k    = vid >> 7;                       // TILES = 128
    const int c    = tile * 256 + threadIdx.x;

    const unsigned epoch = g_epoch;                  // set by prologue launch
    const float wc = __ldg(&w[c & (H - 1)]);
    const float* xp = x + (size_t)k * L * BH + c;

    // Load the whole chunk into registers (the only read of x).
    float buf[L];
#pragma unroll
    for (int i = 0; i < L; i++) buf[i] = __ldcs(xp + i * BH);

    // Chunk summary: h_out = max(M, A + P*h_in)
    float M = (wc > 0.0f) ? __int_as_float(0xff800000) : 0.0f;  // -inf / 0
    float A = 0.0f;
#pragma unroll
    for (int i = 0; i < L; i++) {
        M = fmaxf(0.0f, fmaf(wc, M, buf[i]));
        A = fmaf(wc, A, buf[i]);
    }

    // Acquire h_in: each lane polls ITS OWN packed slot. No block barriers.
    float hin;
    if (k == 0) {
        hin = __ldg(&h0[c]);
    } else {
        unsigned long long* slot = &g_slot[(size_t)(k - 1) * BH + c];
        unsigned long long v = ld_acquire_u64(slot);
        while ((unsigned)(v >> 32) != epoch) {
            __nanosleep(20);
            v = ld_acquire_u64(slot);
        }
        hin = __uint_as_float((unsigned)v);
    }

    // Publish immediately (chain critical path): one packed release store.
    if (k < K - 1) {
        float P = wc;
#pragma unroll
        for (int s = 0; s < 5; s++) P *= P;          // wc^32
        const float hout = fmaxf(M, fmaf(P, hin, A));
        const unsigned long long pk =
            ((unsigned long long)epoch << 32) | __float_as_uint(hout);
        st_release_u64(&g_slot[(size_t)k * BH + c], pk);
    }

    // Emit: exact forward recursion from registers.
    float* op = out + (size_t)k * L * BH + c;
    float h = hin;
#pragma unroll
    for (int i = 0; i < L; i++) {
        h = fmaxf(fmaf(wc, h, buf[i]), 0.0f);
        __stcs(op + i * BH, h);
    }
}

extern "C" void kernel_launch(void* const* d_in, const int* in_sizes, int n_in,
                              void* d_out, int out_size)
{
    const float* x  = (const float*)d_in[0];   // (T, B, H)
    const float* h0 = (const float*)d_in[1];   // (B, H)
    const float* w  = (const float*)d_in[2];   // (H,)
    float* out      = (float*)d_out;

    k_prologue<<<1, 1>>>();
    indrnn_onepass<<<NBLK, 256>>>(x, h0, w, out);
}

// round 8
// speedup vs baseline: 2.1195x; 1.5292x over previous
#include <cuda_runtime.h>

// Single-pass IndRNN scan with CUB-style decoupled lookback (aggregates +
// inclusives). h_t = relu(x_t + w*h_{t-1}), w >= 0.
// Chunk map g(h) = max(M, A + P*h), P = w^L, closed under composition:
//   S∘g: M_S=max(M_S, A_S+P_S*M), A_S=A_S+P_S*A, P_S=P_S*P.
// Each block publishes (M,A) as soon as its x is loaded (no chain dep);
// consumers compose aggregates backward until they hit an inclusive h.

static constexpr int T     = 2048;
static constexpr int B     = 32;
static constexpr int H     = 1024;
static constexpr int BH    = B * H;        // 32768
static constexpr int L     = 32;           // timesteps per chunk (registers)
static constexpr int K     = T / L;        // 64 chunks
static constexpr int TILES = BH / 256;     // 128 channel tiles
static constexpr int NBLK  = TILES * K;    // 8192 blocks

// Slot per (k, c): {M, A, h, status}. status = 2*epoch (agg) | 2*epoch+1 (incl).
__device__ float4   g_slot[(size_t)K * BH];   // 32 MB, L2-resident working set
__device__ unsigned g_epoch;
__device__ unsigned g_ticket;

__global__ void k_prologue()
{
    g_epoch  = g_epoch + 1u;   // fresh slots read as status 0 != 2e, 2e+1
    g_ticket = 0u;
}

__device__ __forceinline__ void st_slot(float4* p, float m, float a, float h,
                                        unsigned status)
{
    asm volatile("st.volatile.global.v4.f32 [%0], {%1, %2, %3, %4};"
                 :: "l"(p), "f"(m), "f"(a), "f"(h),
                    "f"(__uint_as_float(status)) : "memory");
}
__device__ __forceinline__ float4 ld_slot(const float4* p)
{
    float4 v;
    asm volatile("ld.volatile.global.v4.f32 {%0, %1, %2, %3}, [%4];"
                 : "=f"(v.x), "=f"(v.y), "=f"(v.z), "=f"(v.w) : "l"(p)
                 : "memory");
    return v;
}

__global__ __launch_bounds__(256)
void indrnn_onepass(const float* __restrict__ x,
                    const float* __restrict__ h0,
                    const float* __restrict__ w,
                    float* __restrict__ out)
{
    __shared__ unsigned s_vid;
    if (threadIdx.x == 0) s_vid = atomicAdd(&g_ticket, 1u);
    __syncthreads();
    const unsigned vid = s_vid;
    const int tile = vid & (TILES - 1);
    const int k    = vid >> 7;                       // TILES = 128
    const int c    = tile * 256 + threadIdx.x;

    const unsigned epoch = g_epoch;
    const float wc  = __ldg(&w[c & (H - 1)]);
    const float h0c = __ldg(&h0[c]);
    float Pc = wc;
#pragma unroll
    for (int s = 0; s < 5; s++) Pc *= Pc;            // wc^32

    const float* xp = x + (size_t)k * L * BH + c;

    // Load the whole chunk into registers (the only read of x).
    float buf[L];
#pragma unroll
    for (int i = 0; i < L; i++) buf[i] = __ldcs(xp + i * BH);

    // Chunk aggregate: g(h) = max(M, A + Pc*h).
    float M = (wc > 0.0f) ? __int_as_float(0xff800000) : 0.0f;  // -inf / 0
    float A = 0.0f;
#pragma unroll
    for (int i = 0; i < L; i++) {
        M = fmaxf(0.0f, fmaf(wc, M, buf[i]));        // M ends finite
        A = fmaf(wc, A, buf[i]);
    }

    // Publish aggregate IMMEDIATELY (independent of the chain).
    if (k < K - 1)
        st_slot(&g_slot[(size_t)k * BH + c], M, A, 0.0f, 2u * epoch);

    // Lookback: compose aggregates backward until an inclusive (or h0).
    float hin;
    if (k == 0) {
        hin = h0c;
    } else {
        float Ms = __int_as_float(0xff800000);       // identity map
        float As = 0.0f;
        float Ps = 1.0f;
        int   j  = k - 1;
        for (;;) {
            float4 s = ld_slot(&g_slot[(size_t)j * BH + c]);
            unsigned st = __float_as_uint(s.w);
            if (st == 2u * epoch + 1u) {             // inclusive h available
                hin = fmaxf(Ms, fmaf(Ps, s.z, As));
                break;
            }
            if (st == 2u * epoch) {                  // aggregate: compose, step left
                const float nM = fmaxf(Ms, fmaf(Ps, s.x, As));
                As = fmaf(Ps, s.y, As);
                Ms = nM;
                Ps *= Pc;
                if (--j < 0) { hin = fmaxf(Ms, fmaf(Ps, h0c, As)); break; }
                continue;
            }
            __nanosleep(32);                         // predecessor not started yet
        }
    }

    // Publish inclusive (bounds lookback depth for later waves), then emit.
    if (k < K - 1) {
        const float hout = fmaxf(M, fmaf(Pc, hin, A));
        st_slot(&g_slot[(size_t)k * BH + c], M, A, hout, 2u * epoch + 1u);
    }

    float* op = out + (size_t)k * L * BH + c;
    float h = hin;
#pragma unroll
    for (int i = 0; i < L; i++) {
        h = fmaxf(fmaf(wc, h, buf[i]), 0.0f);
        __stcs(op + i * BH, h);
    }
}

extern "C" void kernel_launch(void* const* d_in, const int* in_sizes, int n_in,
                              void* d_out, int out_size)
{
    const float* x  = (const float*)d_in[0];   // (T, B, H)
    const float* h0 = (const float*)d_in[1];   // (B, H)
    const float* w  = (const float*)d_in[2];   // (H,)
    float* out      = (float*)d_out;

    k_prologue<<<1, 1>>>();
    indrnn_onepass<<<NBLK, 256>>>(x, h0, w, out);
}